// round 9
// baseline (speedup 1.0000x reference)
#include <cuda_runtime.h>
#include <stdint.h>

#define BB 64
#define NN 68
#define ZZ 384
#define MM 46
#define DC 7
#define EE (MM*DC)   /* 322 */
#define NITER 10
#define MAXDEG 46

#define CT 96        /* check threads per check: each owns 4 z (one u32) */
#define CM 2         /* checks per CTA */

// prev: check-node output messages, VAR-aligned rows: g_prev[b][e][z]
// (check kernel applies the edge shift at store time via smem staging)
__device__ __align__(128) int8_t g_prev[BB * EE * ZZ];   // ~7.9 MB
// x2: quantized check inputs, VAR-aligned rows:         g_x2[b][e][z]
__device__ __align__(128) int8_t g_x2[BB * EE * ZZ];     // ~7.9 MB
// CSR: variable -> incident edge row offsets (e * ZZ)
__device__ int g_var_deg[NN];
__device__ int g_var_off[NN * MAXDEG];

// ---------------------------------------------------------------------------
// CSR setup (atomic scatter; order-independent because sums are integer-exact)
// ---------------------------------------------------------------------------
__global__ void setup_csr(const int* __restrict__ etv) {
    const int t = threadIdx.x;
    if (t < NN) g_var_deg[t] = 0;
    __syncthreads();
    if (t < EE) {
        const int n = etv[t];
        const int slot = atomicAdd(&g_var_deg[n], 1);
        g_var_off[n * MAXDEG + slot] = t * ZZ;
    }
}

// quantize value scaled by 16: code = sign(d) * min(rint(|d|), 31), as byte
__device__ __forceinline__ uint32_t qbyte(float d) {
    const float q = fminf(rintf(fabsf(d)), 31.0f);
    const int c = (int)(d < 0.0f ? -q : q);
    return (uint32_t)c & 0xFFu;
}

// ---------------------------------------------------------------------------
// Initial x2(0) = Q(xa) codes, var-aligned. Grid (E, B) x 96 threads.
// ---------------------------------------------------------------------------
__global__ void __launch_bounds__(CT)
init_x2(const float* __restrict__ xa, const int* __restrict__ etv) {
    const int e = blockIdx.x;
    const int b = blockIdx.y;
    const int t = threadIdx.x;
    const int v = etv[e];
    const float4 xv = *(const float4*)(xa + (size_t)(b * NN + v) * ZZ + 4 * t);
    const uint32_t w = qbyte(xv.x * 16.0f)
                     | (qbyte(xv.y * 16.0f) << 8)
                     | (qbyte(xv.z * 16.0f) << 16)
                     | (qbyte(xv.w * 16.0f) << 24);
    *(uint32_t*)(g_x2 + (size_t)(b * EE + e) * ZZ + 4 * t) = w;
}

// ---------------------------------------------------------------------------
// Check kernel: int8 SIMD min-sum, 4 z per thread packed in u32.
// Reads x2 var-aligned (funnel shift by edge shift s, index b0 = 4t+s).
// Writes prev VAR-ALIGNED: rotated message bytes staged in smem (each byte
// written exactly once -> race-free), then copied out as aligned u32.
// ---------------------------------------------------------------------------
__global__ void __launch_bounds__(CT * CM)
check_kernel(const int* __restrict__ shift,
             const float* __restrict__ cnw,
             int it) {
    const int m  = blockIdx.x * CM + threadIdx.y;
    const int b  = blockIdx.y;
    const int t  = threadIdx.x;
    const int ty = threadIdx.y;

    __shared__ uint8_t  lutb[32];
    __shared__ uint32_t stage[CM][DC][CT];   // rotated message rows (384B each)
    if (ty == 0 && t < 32) {
        const float w = cnw[it];
        lutb[t] = (uint8_t)(int)fminf(rintf(w * (float)t), 31.0f);
    }
    __syncthreads();

    const int8_t* __restrict__ xb = g_x2 + (size_t)(b * EE + m * DC) * ZZ;

    int b0[DC];
    uint32_t c[DC];
#pragma unroll
    for (int j = 0; j < DC; ++j) {
        const int s = shift[m * DC + j];
        int byte0 = 4 * t + s;
        if (byte0 >= ZZ) byte0 -= ZZ;
        b0[j] = byte0;
        const int i0 = byte0 >> 2;
        int i1 = i0 + 1;
        if (i1 == ZZ / 4) i1 = 0;
        const uint32_t* p = (const uint32_t*)(xb + j * ZZ);
        c[j] = __funnelshift_r(p[i0], p[i1], (byte0 & 3) * 8);
    }

    uint32_t a[DC];
#pragma unroll
    for (int j = 0; j < DC; ++j) a[j] = __vabs4(c[j]);
    uint32_t m1 = a[0];
#pragma unroll
    for (int j = 1; j < DC; ++j) m1 = __vminu4(m1, a[j]);

    uint32_t eq[DC], cnt = 0, m2 = 0xFFFFFFFFu;
#pragma unroll
    for (int j = 0; j < DC; ++j) {
        eq[j] = __vcmpeq4(a[j], m1);
        cnt  += eq[j] & 0x01010101u;
        m2    = __vminu4(m2, a[j] | eq[j]);
    }
    const uint32_t unique = __vcmpeq4(cnt, 0x01010101u);
    m2 = __vminu4(m2, 0x1F1F1F1Fu);

    uint32_t tot = c[0];
#pragma unroll
    for (int j = 1; j < DC; ++j) tot ^= c[j];

    const uint32_t q1 =  (uint32_t)lutb[ m1        & 31]
                      | ((uint32_t)lutb[(m1 >> 8)  & 31] << 8)
                      | ((uint32_t)lutb[(m1 >> 16) & 31] << 16)
                      | ((uint32_t)lutb[(m1 >> 24) & 31] << 24);
    const uint32_t q2 =  (uint32_t)lutb[ m2        & 31]
                      | ((uint32_t)lutb[(m2 >> 8)  & 31] << 8)
                      | ((uint32_t)lutb[(m2 >> 16) & 31] << 16)
                      | ((uint32_t)lutb[(m2 >> 24) & 31] << 24);

#pragma unroll
    for (int j = 0; j < DC; ++j) {
        const uint32_t sel  = eq[j] & unique;
        const uint32_t q    = (q2 & sel) | (q1 & ~sel);
        const uint32_t nm   = __vcmpgts4(0u, tot ^ c[j]);
        const uint32_t outw = __vsub4(q ^ nm, nm);
        uint8_t* s8 = (uint8_t*)stage[ty][j];
#pragma unroll
        for (int k = 0; k < 4; ++k) {
            int bk = b0[j] + k;
            if (bk >= ZZ) bk -= ZZ;
            s8[bk] = (uint8_t)(outw >> (8 * k));
        }
    }
    __syncthreads();

    int8_t* __restrict__ pv = g_prev + (size_t)(b * EE + m * DC) * ZZ + 4 * t;
#pragma unroll
    for (int j = 0; j < DC; ++j)
        *(uint32_t*)(pv + j * ZZ) = stage[ty][j][t];
}

// ---------------------------------------------------------------------------
// Variable kernel: shift-free, 3 u32 (12 z) per thread.
// Block 128 = 32 z-u32 lanes x 4 n (one n per warp, full Z row per CTA).
// Grid (17, B). Sum via xor-bias 16-bit-lane accumulation (exact).
// EMIT: k = float2int_rn(clamp(t16,+-63) - c), packed, clamped, u32 store.
// ---------------------------------------------------------------------------
template <bool EMIT>
__global__ void __launch_bounds__(128)
var_kernel(const float* __restrict__ xa, float* __restrict__ out_slice) {
    const int b   = blockIdx.y;
    const int n0  = blockIdx.x * 4;
    const int tx  = threadIdx.x & 31;       // z u32 lane
    const int ty  = threadIdx.x >> 5;       // n within group
    const int zb  = 4 * tx;                 // first z byte (others +128, +256)
    const int n   = n0 + ty;
    const int bbase = b * EE * ZZ;

    __shared__ float tile[4][388];

    const int d = g_var_deg[n];
    const int* __restrict__ ol = &g_var_off[n * MAXDEG];

    uint32_t accE[3] = {0, 0, 0}, accO[3] = {0, 0, 0};
    for (int i = 0; i < d; ++i) {
        const uint32_t* p = (const uint32_t*)(g_prev + bbase + ol[i] + zb);
#pragma unroll
        for (int u = 0; u < 3; ++u) {
            const uint32_t c = p[32 * u] ^ 0x80808080u;
            accE[u] += c & 0x00FF00FFu;          // bytes 0,2 (biased)
            accO[u] += (c >> 8) & 0x00FF00FFu;   // bytes 1,3 (biased)
        }
    }
    const int bias = d << 7;                     // 128 * d per lane

    const float* __restrict__ xrow = xa + (size_t)(b * NN + n) * ZZ + zb;
    float t16[12];
#pragma unroll
    for (int u = 0; u < 3; ++u) {
        const float4 xv = *(const float4*)(xrow + 128 * u);
        t16[4*u+0] = fmaf(xv.x, 16.0f, (float)((int)(accE[u] & 0xFFFFu) - bias));
        t16[4*u+1] = fmaf(xv.y, 16.0f, (float)((int)(accO[u] & 0xFFFFu) - bias));
        t16[4*u+2] = fmaf(xv.z, 16.0f, (float)((int)(accE[u] >> 16)     - bias));
        t16[4*u+3] = fmaf(xv.w, 16.0f, (float)((int)(accO[u] >> 16)     - bias));
        float4 ov;
        ov.x = t16[4*u+0] * 0.0625f; ov.y = t16[4*u+1] * 0.0625f;
        ov.z = t16[4*u+2] * 0.0625f; ov.w = t16[4*u+3] * 0.0625f;
        *(float4*)&tile[ty][zb + 128 * u] = ov;
    }

    if (EMIT) {
        float tc[12];
#pragma unroll
        for (int q = 0; q < 12; ++q)
            tc[q] = fminf(fmaxf(t16[q], -63.0f), 63.0f);   // output-invariant clamp
        for (int i = 0; i < d; ++i) {
            const int off = bbase + ol[i] + zb;
            const uint32_t* p = (const uint32_t*)(g_prev + off);
#pragma unroll
            for (int u = 0; u < 3; ++u) {
                const uint32_t c = p[32 * u];                // L1 hit
                const int k0 = __float2int_rn(tc[4*u+0] - (float)(int)(int8_t)(c));
                const int k1 = __float2int_rn(tc[4*u+1] - (float)(int)(int8_t)(c >> 8));
                const int k2 = __float2int_rn(tc[4*u+2] - (float)(int)(int8_t)(c >> 16));
                const int k3 = __float2int_rn(tc[4*u+3] - (float)(int)(int8_t)(c >> 24));
                const uint32_t p1 = __byte_perm((uint32_t)k0, (uint32_t)k1, 0x0040);
                const uint32_t p2 = __byte_perm((uint32_t)k2, (uint32_t)k3, 0x0040);
                uint32_t pk = __byte_perm(p1, p2, 0x5410);
                pk = __vmins4(__vmaxs4(pk, 0xE1E1E1E1u), 0x1F1F1F1Fu);
                *(uint32_t*)(g_x2 + off + 128 * u) = pk;
            }
        }
    }
    __syncthreads();

    // out [b][z][n0..n0+3]: one float4 per (thread, u), 16B-aligned (68 = 17*4)
#pragma unroll
    for (int u = 0; u < 3; ++u) {
        const int zl = threadIdx.x + 128 * u;    // 0..383
        float4 val;
        val.x = tile[0][zl];
        val.y = tile[1][zl];
        val.z = tile[2][zl];
        val.w = tile[3][zl];
        *(float4*)(out_slice + (size_t)(b * ZZ + zl) * NN + n0) = val;
    }
}

// ---------------------------------------------------------------------------
// Launch
// ---------------------------------------------------------------------------
extern "C" void kernel_launch(void* const* d_in, const int* in_sizes, int n_in,
                              void* d_out, int out_size) {
    const float* xa    = (const float*)d_in[0];   // (B, N, Z) f32
    const float* cnw   = (const float*)d_in[1];   // (ITERS,) f32
    const int*   etv   = (const int*)d_in[2];     // (E,) i32
    // d_in[3] = edge_to_check — grouping is implicit (repeat(arange(M), 7))
    const int*   shift = (const int*)d_in[4];     // (E,) i32
    float* out = (float*)d_out;                   // (ITERS, B, Z, N) f32

    setup_csr<<<1, EE>>>(etv);
    init_x2<<<dim3(EE, BB), CT>>>(xa, etv);

    const dim3 cgrid(MM / CM, BB);
    const dim3 cblock(CT, CM);
    const dim3 vgrid(17, BB);
    const size_t slice = (size_t)BB * ZZ * NN;

    for (int it = 0; it < NITER; ++it) {
        check_kernel<<<cgrid, cblock>>>(shift, cnw, it);
        if (it < NITER - 1)
            var_kernel<true><<<vgrid, 128>>>(xa, out + (size_t)it * slice);
        else
            var_kernel<false><<<vgrid, 128>>>(xa, out + (size_t)it * slice);
    }
}

// round 10
// speedup vs baseline: 1.1915x; 1.1915x over previous
#include <cuda_runtime.h>
#include <stdint.h>

#define BB 64
#define NN 68
#define ZZ 384
#define MM 46
#define DC 7
#define EE (MM*DC)   /* 322 */
#define NITER 10
#define MAXDEG 46

#define CT 96        /* check threads per check: each owns 4 z (one u32) */
#define CM 2         /* checks per CTA */

// prev: check-node output messages, VAR-aligned rows: g_prev[b][e][z]
// (check kernel applies the edge shift at store time via smem staging)
__device__ __align__(128) int8_t g_prev[BB * EE * ZZ];   // ~7.9 MB
// x2: quantized check inputs, VAR-aligned rows:         g_x2[b][e][z]
__device__ __align__(128) int8_t g_x2[BB * EE * ZZ];     // ~7.9 MB
// CSR: variable -> incident edge row offsets (e * ZZ)
__device__ int g_var_deg[NN];
__device__ int g_var_off[NN * MAXDEG];

// ---------------------------------------------------------------------------
// CSR setup (atomic scatter; order-independent because sums are integer-exact)
// ---------------------------------------------------------------------------
__global__ void setup_csr(const int* __restrict__ etv) {
    const int t = threadIdx.x;
    if (t < NN) g_var_deg[t] = 0;
    __syncthreads();
    if (t < EE) {
        const int n = etv[t];
        const int slot = atomicAdd(&g_var_deg[n], 1);
        g_var_off[n * MAXDEG + slot] = t * ZZ;
    }
}

// quantize value scaled by 16: code = sign(d) * min(rint(|d|), 31), as byte
__device__ __forceinline__ uint32_t qbyte(float d) {
    const float q = fminf(rintf(fabsf(d)), 31.0f);
    const int c = (int)(d < 0.0f ? -q : q);
    return (uint32_t)c & 0xFFu;
}

// ---------------------------------------------------------------------------
// Initial x2(0) = Q(xa) codes, var-aligned. Grid (E, B) x 96 threads.
// ---------------------------------------------------------------------------
__global__ void __launch_bounds__(CT)
init_x2(const float* __restrict__ xa, const int* __restrict__ etv) {
    const int e = blockIdx.x;
    const int b = blockIdx.y;
    const int t = threadIdx.x;
    const int v = etv[e];
    const float4 xv = *(const float4*)(xa + (size_t)(b * NN + v) * ZZ + 4 * t);
    const uint32_t w = qbyte(xv.x * 16.0f)
                     | (qbyte(xv.y * 16.0f) << 8)
                     | (qbyte(xv.z * 16.0f) << 16)
                     | (qbyte(xv.w * 16.0f) << 24);
    *(uint32_t*)(g_x2 + (size_t)(b * EE + e) * ZZ + 4 * t) = w;
}

// ---------------------------------------------------------------------------
// Check kernel: int8 SIMD min-sum, 4 z per thread packed in u32.
// Reads x2 var-aligned (funnel shift by edge shift s, index b0 = 4t+s).
// Writes prev VAR-ALIGNED: rotated message bytes staged in smem (each byte
// written exactly once -> race-free), then copied out as aligned u32.
// ---------------------------------------------------------------------------
__global__ void __launch_bounds__(CT * CM)
check_kernel(const int* __restrict__ shift,
             const float* __restrict__ cnw,
             int it) {
    const int m  = blockIdx.x * CM + threadIdx.y;
    const int b  = blockIdx.y;
    const int t  = threadIdx.x;
    const int ty = threadIdx.y;

    __shared__ uint8_t  lutb[32];
    __shared__ uint32_t stage[CM][DC][CT];   // rotated message rows (384B each)
    if (ty == 0 && t < 32) {
        const float w = cnw[it];
        lutb[t] = (uint8_t)(int)fminf(rintf(w * (float)t), 31.0f);
    }
    __syncthreads();

    const int8_t* __restrict__ xb = g_x2 + (size_t)(b * EE + m * DC) * ZZ;

    int b0[DC];
    uint32_t c[DC];
#pragma unroll
    for (int j = 0; j < DC; ++j) {
        const int s = shift[m * DC + j];
        int byte0 = 4 * t + s;
        if (byte0 >= ZZ) byte0 -= ZZ;
        b0[j] = byte0;
        const int i0 = byte0 >> 2;
        int i1 = i0 + 1;
        if (i1 == ZZ / 4) i1 = 0;
        const uint32_t* p = (const uint32_t*)(xb + j * ZZ);
        c[j] = __funnelshift_r(p[i0], p[i1], (byte0 & 3) * 8);
    }

    uint32_t a[DC];
#pragma unroll
    for (int j = 0; j < DC; ++j) a[j] = __vabs4(c[j]);
    uint32_t m1 = a[0];
#pragma unroll
    for (int j = 1; j < DC; ++j) m1 = __vminu4(m1, a[j]);

    uint32_t eq[DC], cnt = 0, m2 = 0xFFFFFFFFu;
#pragma unroll
    for (int j = 0; j < DC; ++j) {
        eq[j] = __vcmpeq4(a[j], m1);
        cnt  += eq[j] & 0x01010101u;
        m2    = __vminu4(m2, a[j] | eq[j]);
    }
    const uint32_t unique = __vcmpeq4(cnt, 0x01010101u);
    m2 = __vminu4(m2, 0x1F1F1F1Fu);

    uint32_t tot = c[0];
#pragma unroll
    for (int j = 1; j < DC; ++j) tot ^= c[j];

    const uint32_t q1 =  (uint32_t)lutb[ m1        & 31]
                      | ((uint32_t)lutb[(m1 >> 8)  & 31] << 8)
                      | ((uint32_t)lutb[(m1 >> 16) & 31] << 16)
                      | ((uint32_t)lutb[(m1 >> 24) & 31] << 24);
    const uint32_t q2 =  (uint32_t)lutb[ m2        & 31]
                      | ((uint32_t)lutb[(m2 >> 8)  & 31] << 8)
                      | ((uint32_t)lutb[(m2 >> 16) & 31] << 16)
                      | ((uint32_t)lutb[(m2 >> 24) & 31] << 24);

#pragma unroll
    for (int j = 0; j < DC; ++j) {
        const uint32_t sel  = eq[j] & unique;
        const uint32_t q    = (q2 & sel) | (q1 & ~sel);
        const uint32_t nm   = __vcmpgts4(0u, tot ^ c[j]);
        const uint32_t outw = __vsub4(q ^ nm, nm);
        uint8_t* s8 = (uint8_t*)stage[ty][j];
#pragma unroll
        for (int k = 0; k < 4; ++k) {
            int bk = b0[j] + k;
            if (bk >= ZZ) bk -= ZZ;
            s8[bk] = (uint8_t)(outw >> (8 * k));
        }
    }
    __syncthreads();

    int8_t* __restrict__ pv = g_prev + (size_t)(b * EE + m * DC) * ZZ + 4 * t;
#pragma unroll
    for (int j = 0; j < DC; ++j)
        *(uint32_t*)(pv + j * ZZ) = stage[ty][j][t];
}

// ---------------------------------------------------------------------------
// Variable kernel: shift-free. Block 128 = 32 z-u32 lanes x 4 n (one n per
// warp). Grid (3, 17, B). xa load hoisted to overlap DRAM latency with the
// prev sum loop. out written with streaming stores (no L2 pollution).
// ---------------------------------------------------------------------------
template <bool EMIT>
__global__ void __launch_bounds__(128)
var_kernel(const float* __restrict__ xa, float* __restrict__ out_slice) {
    const int b   = blockIdx.z;
    const int n0  = blockIdx.y * 4;
    const int zu0 = blockIdx.x * 32;        // u32 units; z0 = 4*zu0
    const int tx  = threadIdx.x & 31;       // z u32 lane
    const int ty  = threadIdx.x >> 5;       // n within group
    const int zb  = 4 * (zu0 + tx);         // z byte index
    const int n   = n0 + ty;
    const int bbase = b * EE * ZZ;

    __shared__ float tile[4][132];

    // issue the (possibly DRAM) xa load FIRST so it overlaps the prev loads
    const float4 xv = __ldg((const float4*)(xa + (size_t)(b * NN + n) * ZZ + zb));

    const int d = g_var_deg[n];
    const int* __restrict__ ol = &g_var_off[n * MAXDEG];

    uint32_t accE = 0, accO = 0;            // (byte ^ 0x80) sums in 16-bit lanes
    for (int i = 0; i < d; ++i) {
        const uint32_t c = *(const uint32_t*)(g_prev + bbase + ol[i] + zb)
                         ^ 0x80808080u;
        accE += c & 0x00FF00FFu;            // bytes 0,2
        accO += (c >> 8) & 0x00FF00FFu;     // bytes 1,3
    }
    const int bias = d << 7;                // 128 * d per lane
    const float s0 = (float)((int)(accE & 0xFFFFu) - bias);
    const float s1 = (float)((int)(accO & 0xFFFFu) - bias);
    const float s2 = (float)((int)(accE >> 16)     - bias);
    const float s3 = (float)((int)(accO >> 16)     - bias);

    const float t0 = fmaf(xv.x, 16.0f, s0);
    const float t1 = fmaf(xv.y, 16.0f, s1);
    const float t2 = fmaf(xv.z, 16.0f, s2);
    const float t3 = fmaf(xv.w, 16.0f, s3);

    float4 ov;
    ov.x = t0 * 0.0625f; ov.y = t1 * 0.0625f;
    ov.z = t2 * 0.0625f; ov.w = t3 * 0.0625f;
    *(float4*)&tile[ty][4 * tx] = ov;
    __syncthreads();

    // out [b][z][n0..n0+3]: one streaming float4 per thread (write-once data)
    {
        const int zl = threadIdx.x;         // 0..127
        float4 val;
        val.x = tile[0][zl];
        val.y = tile[1][zl];
        val.z = tile[2][zl];
        val.w = tile[3][zl];
        __stcs((float4*)(out_slice + (size_t)(b * ZZ + 4 * zu0 + zl) * NN + n0), val);
    }

    if (EMIT) {
        // pre-clamp so k fits int8; output-invariant (|t|>=63 -> code 31)
        const float tc0 = fminf(fmaxf(t0, -63.0f), 63.0f);
        const float tc1 = fminf(fmaxf(t1, -63.0f), 63.0f);
        const float tc2 = fminf(fmaxf(t2, -63.0f), 63.0f);
        const float tc3 = fminf(fmaxf(t3, -63.0f), 63.0f);
        for (int i = 0; i < d; ++i) {
            const int off = bbase + ol[i] + zb;
            const uint32_t c = *(const uint32_t*)(g_prev + off);   // L1 hit
            const int k0 = __float2int_rn(tc0 - (float)(int)(int8_t)(c));
            const int k1 = __float2int_rn(tc1 - (float)(int)(int8_t)(c >> 8));
            const int k2 = __float2int_rn(tc2 - (float)(int)(int8_t)(c >> 16));
            const int k3 = __float2int_rn(tc3 - (float)(int)(int8_t)(c >> 24));
            const uint32_t p1 = __byte_perm((uint32_t)k0, (uint32_t)k1, 0x0040);
            const uint32_t p2 = __byte_perm((uint32_t)k2, (uint32_t)k3, 0x0040);
            uint32_t pk = __byte_perm(p1, p2, 0x5410);
            pk = __vmins4(__vmaxs4(pk, 0xE1E1E1E1u), 0x1F1F1F1Fu);
            *(uint32_t*)(g_x2 + off) = pk;
        }
    }
}

// ---------------------------------------------------------------------------
// Launch
// ---------------------------------------------------------------------------
extern "C" void kernel_launch(void* const* d_in, const int* in_sizes, int n_in,
                              void* d_out, int out_size) {
    const float* xa    = (const float*)d_in[0];   // (B, N, Z) f32
    const float* cnw   = (const float*)d_in[1];   // (ITERS,) f32
    const int*   etv   = (const int*)d_in[2];     // (E,) i32
    // d_in[3] = edge_to_check — grouping is implicit (repeat(arange(M), 7))
    const int*   shift = (const int*)d_in[4];     // (E,) i32
    float* out = (float*)d_out;                   // (ITERS, B, Z, N) f32

    setup_csr<<<1, EE>>>(etv);
    init_x2<<<dim3(EE, BB), CT>>>(xa, etv);

    const dim3 cgrid(MM / CM, BB);
    const dim3 cblock(CT, CM);
    const dim3 vgrid(3, 17, BB);
    const size_t slice = (size_t)BB * ZZ * NN;

    for (int it = 0; it < NITER; ++it) {
        check_kernel<<<cgrid, cblock>>>(shift, cnw, it);
        if (it < NITER - 1)
            var_kernel<true><<<vgrid, 128>>>(xa, out + (size_t)it * slice);
        else
            var_kernel<false><<<vgrid, 128>>>(xa, out + (size_t)it * slice);
    }
}